// round 12
// baseline (speedup 1.0000x reference)
#include <cuda_runtime.h>

// Problem constants (fixed by setup_inputs: N=50000, E=800000, D=100, 2 layers)
#define NMAX 50000
#define EMAX 800000
#define DD   100
#define C4   25      // D/4 float4 chunks per dense row (feat / output)
#define CP   32      // pitched float4 chunks per internal row (512B, line-aligned)
#define WPITCH 104   // padded pitch (floats) for transposed W rows
#define NCHUNK 4     // spmm0/gemm1 overlap chunks

typedef unsigned long long u64;

// ---- static device scratch (no runtime allocation allowed) ----
__device__ float g_bufA[NMAX * CP * 4];    // gemm0 output (spmm0 gather source)
__device__ float g_bufB[NMAX * CP * 4];    // spmm0 output x1 (gemm1 input)
__device__ float g_bufD[NMAX * CP * 4];    // gemm1 output (spmm1 gather source)
__device__ float g_Wt[2 * DD * WPITCH];    // k-major transposed weights
__device__ int   g_cnt[NMAX];              // per-row edge counts
__device__ int   g_rowptr[NMAX + 1];       // CSR row pointers
__device__ float g_deginv[NMAX];           // 1/(cnt+1)  (self loop included)
__device__ int   g_col[EMAX];              // CSR column (src) indices
__device__ int   g_rank[EMAX];             // per-edge rank within its dst row
__device__ float g_sfac[NMAX];             // layer-0 per-row 1/max(norm,eps)
__device__ int   g_bsums[64];              // scan block sums

// ---------------- f32x2 helpers ----------------
__device__ __forceinline__ u64 dup2(float a) {
    u64 r; unsigned ai = __float_as_uint(a);
    asm("mov.b64 %0, {%1, %1};" : "=l"(r) : "r"(ai));
    return r;
}
__device__ __forceinline__ void ffma2(u64& acc, u64 a, u64 b) {
    asm("fma.rn.f32x2 %0, %1, %2, %0;" : "+l"(acc) : "l"(a), "l"(b));
}
__device__ __forceinline__ float2 unpk(u64 v) {
    unsigned lo, hi;
    asm("mov.b64 {%0, %1}, %2;" : "=r"(lo), "=r"(hi) : "l"(v));
    return make_float2(__uint_as_float(lo), __uint_as_float(hi));
}

// ---------------- preprocessing ----------------

// zero counts, transpose W (k-major, padded pitch)
__global__ void init_k(const float* __restrict__ W, int N) {
    int i = blockIdx.x * blockDim.x + threadIdx.x;
    if (i < N) g_cnt[i] = 0;
    if (i < 2 * DD * DD) {
        int l = i / (DD * DD);
        int r = i - l * DD * DD;
        int j = r / DD;
        int k = r - j * DD;
        g_Wt[l * DD * WPITCH + k * WPITCH + j] = W[i];
    }
}

// histogram; the atomic's return value is the edge's rank within its row
__global__ void count_k(const int* __restrict__ dst, int E) {
    int i = blockIdx.x * blockDim.x + threadIdx.x;
    if (i < E) g_rank[i] = atomicAdd(&g_cnt[__ldg(&dst[i])], 1);
}

// scanA: per-1024-block exclusive scan (shfl-based), block totals -> g_bsums
__global__ void __launch_bounds__(1024) scanA_k(int N) {
    __shared__ int wsum[32];
    int tid = threadIdx.x, bid = blockIdx.x;
    int lane = tid & 31, wid = tid >> 5;
    int i = bid * 1024 + tid;
    int v = (i < N) ? g_cnt[i] : 0;

    int x = v;
    #pragma unroll
    for (int o = 1; o < 32; o <<= 1) {
        int t = __shfl_up_sync(0xffffffffu, x, o);
        if (lane >= o) x += t;
    }
    if (lane == 31) wsum[wid] = x;
    __syncthreads();
    if (wid == 0) {
        int s = wsum[lane];
        #pragma unroll
        for (int o = 1; o < 32; o <<= 1) {
            int t = __shfl_up_sync(0xffffffffu, s, o);
            if (lane >= o) s += t;
        }
        wsum[lane] = s;                     // inclusive scan of warp sums
    }
    __syncthreads();
    int excl = x - v + (wid ? wsum[wid - 1] : 0);

    if (i < N) {
        g_rowptr[i] = excl;                 // block-local exclusive
        g_deginv[i] = 1.0f / (float)(v + 1);
    }
    // FIX (R9 bug): block total is wsum[31], NOT warp-local x at tid 1023
    if (tid == 0) g_bsums[bid] = wsum[31];
}

// scanC: each block adds the sum of its predecessor block totals (no spin)
__global__ void __launch_bounds__(1024) scanC_k(int N, int E) {
    __shared__ int s_off;
    int tid = threadIdx.x, bid = blockIdx.x;
    if (tid < 32) {
        int sum = 0;
        for (int p = tid; p < bid; p += 32) sum += g_bsums[p];
        #pragma unroll
        for (int o = 16; o; o >>= 1) sum += __shfl_xor_sync(0xffffffffu, sum, o);
        if (tid == 0) s_off = sum;
    }
    __syncthreads();
    int i = bid * 1024 + tid;
    if (i < N) g_rowptr[i] += s_off;
    if (i == 0) g_rowptr[N] = E;
}

// atomic-free CSR scatter: pos = rowptr[dst] + rank
__global__ void scatter_k(const int* __restrict__ src, const int* __restrict__ dst, int E) {
    int i = blockIdx.x * blockDim.x + threadIdx.x;
    if (i < E) {
        int d = __ldg(&dst[i]);
        int pos = __ldg(&g_rowptr[d]) + g_rank[i];
        g_col[pos] = __ldg(&src[i]);
    }
}

// ---------------- GEMM: yout[rbase..rend) = x @ W[layer]^T  (packed f32x2) ----------------
// 60 rows per CTA; 250 active threads: cg = tid%25 (4 output cols), rg = tid/25
// (6 rows each). W tile (k-major) in SMEM: cg lanes read contiguous 16B ->
// conflict-free; each float4 yields two naturally-packed f32x2 column pairs.
__global__ void __launch_bounds__(256) gemm_k(const float* __restrict__ xin, int xs4,
                                              int layer, float4* __restrict__ yout,
                                              int rbase, int rend) {
    __shared__ float Ws[DD * WPITCH];   // 41.6 KB
    const float* wt = g_Wt + layer * DD * WPITCH;
    for (int i = threadIdx.x; i < DD * WPITCH; i += 256) Ws[i] = wt[i];
    __syncthreads();

    int tid = threadIdx.x;
    if (tid >= 250) return;
    int cg = tid % 25;
    int rg = tid / 25;                 // 0..9
    int row0 = rbase + blockIdx.x * 60 + rg * 6;

    const float4* x4 = (const float4*)xin;
    const double2* Wd = (const double2*)Ws;   // pitch: 26 double2 per k-row

    u64 a01[6], a23[6];
    int ridx[6];
    #pragma unroll
    for (int i = 0; i < 6; ++i) {
        a01[i] = 0ull; a23[i] = 0ull;
        int r = row0 + i;
        ridx[i] = (r < rend) ? r : rbase;  // clamp for safe loads; store guarded
    }

    #pragma unroll 1
    for (int k4 = 0; k4 < 25; ++k4) {
        u64 w01[4], w23[4];
        #pragma unroll
        for (int kk = 0; kk < 4; ++kk) {
            double2 t = Wd[(k4 * 4 + kk) * 26 + cg];
            w01[kk] = __double_as_longlong(t.x);
            w23[kk] = __double_as_longlong(t.y);
        }
        #pragma unroll
        for (int i = 0; i < 6; ++i) {
            float4 xv = __ldg(&x4[ridx[i] * xs4 + k4]);
            u64 d0 = dup2(xv.x), d1 = dup2(xv.y), d2 = dup2(xv.z), d3 = dup2(xv.w);
            ffma2(a01[i], d0, w01[0]); ffma2(a23[i], d0, w23[0]);
            ffma2(a01[i], d1, w01[1]); ffma2(a23[i], d1, w23[1]);
            ffma2(a01[i], d2, w01[2]); ffma2(a23[i], d2, w23[2]);
            ffma2(a01[i], d3, w01[3]); ffma2(a23[i], d3, w23[3]);
        }
    }

    #pragma unroll
    for (int i = 0; i < 6; ++i) {
        int r = row0 + i;
        if (r < rend) {
            float2 lo = unpk(a01[i]);
            float2 hi = unpk(a23[i]);
            yout[r * CP + cg] = make_float4(lo.x, lo.y, hi.x, hi.y);
        }
    }
}

// ---------------- shared SpMM core: acc = deg_inv*(self + gathered sum) ----------------
__device__ __forceinline__ float4 spmm_row(const float4* __restrict__ x4,
                                           int gw, int lane, bool act) {
    float4 acc = make_float4(0.f, 0.f, 0.f, 0.f);
    if (act) acc = __ldg(&x4[gw * CP + lane]);     // self loop

    int beg = g_rowptr[gw];
    int end = g_rowptr[gw + 1];
    for (int base = beg; base < end; base += 32) {
        int idx = base + lane;
        int c = (idx < end) ? __ldg(&g_col[idx]) : 0;
        int m = end - base; if (m > 32) m = 32;
        int j = 0;
        for (; j + 3 < m; j += 4) {                // 4 gathers in flight
            int s0 = __shfl_sync(0xffffffffu, c, j);
            int s1 = __shfl_sync(0xffffffffu, c, j + 1);
            int s2 = __shfl_sync(0xffffffffu, c, j + 2);
            int s3 = __shfl_sync(0xffffffffu, c, j + 3);
            if (act) {
                float4 v0 = __ldg(&x4[s0 * CP + lane]);
                float4 v1 = __ldg(&x4[s1 * CP + lane]);
                float4 v2 = __ldg(&x4[s2 * CP + lane]);
                float4 v3 = __ldg(&x4[s3 * CP + lane]);
                acc.x += v0.x + v1.x; acc.y += v0.y + v1.y;
                acc.z += v0.z + v1.z; acc.w += v0.w + v1.w;
                acc.x += v2.x + v3.x; acc.y += v2.y + v3.y;
                acc.z += v2.z + v3.z; acc.w += v2.w + v3.w;
            }
        }
        for (; j < m; ++j) {
            int s0 = __shfl_sync(0xffffffffu, c, j);
            if (act) {
                float4 v0 = __ldg(&x4[s0 * CP + lane]);
                acc.x += v0.x; acc.y += v0.y; acc.z += v0.z; acc.w += v0.w;
            }
        }
    }

    float dinv = g_deginv[gw];
    acc.x *= dinv; acc.y *= dinv; acc.z *= dinv; acc.w *= dinv;
    return acc;
}

// layer 0 (row chunk [rbase, rend)): bufB = x1 (fp32) + sfac
__global__ void __launch_bounds__(256) spmm0_k(int rbase, int rend) {
    int gw = rbase + ((blockIdx.x * blockDim.x + threadIdx.x) >> 5);
    int lane = threadIdx.x & 31;
    if (gw >= rend) return;
    bool act = lane < C4;

    float4 acc = spmm_row((const float4*)g_bufA, gw, lane, act);

    if (act) ((float4*)g_bufB)[gw * CP + lane] = acc;

    float p = act ? (acc.x * acc.x + acc.y * acc.y + acc.z * acc.z + acc.w * acc.w) : 0.f;
    #pragma unroll
    for (int o = 16; o; o >>= 1) p += __shfl_xor_sync(0xffffffffu, p, o);
    if (lane == 0) g_sfac[gw] = 1.0f / fmaxf(sqrtf(p), 1e-12f);
}

// layer 1 + fused finale: avg[r] = (feat[r] + s1*x1[r] + s2*x2[r]) / 3
__global__ void __launch_bounds__(256) spmm1_k(const float* __restrict__ feat,
                                               float* __restrict__ avg, int N) {
    int gw = (blockIdx.x * blockDim.x + threadIdx.x) >> 5;
    int lane = threadIdx.x & 31;
    if (gw >= N) return;
    bool act = lane < C4;

    float4 acc = spmm_row((const float4*)g_bufD, gw, lane, act);   // x2 row

    float p = act ? (acc.x * acc.x + acc.y * acc.y + acc.z * acc.z + acc.w * acc.w) : 0.f;
    #pragma unroll
    for (int o = 16; o; o >>= 1) p += __shfl_xor_sync(0xffffffffu, p, o);
    float s2 = __shfl_sync(0xffffffffu,
                           (lane == 0) ? (1.0f / fmaxf(sqrtf(p), 1e-12f)) : 0.f, 0);

    if (act) {
        float s1 = __ldg(&g_sfac[gw]);
        float4 f  = ((const float4*)feat)[gw * C4 + lane];
        float4 x1 = ((const float4*)g_bufB)[gw * CP + lane];
        const float k = 1.0f / 3.0f;
        float4 o;
        o.x = (f.x + s1 * x1.x + s2 * acc.x) * k;
        o.y = (f.y + s1 * x1.y + s2 * acc.y) * k;
        o.z = (f.z + s1 * x1.z + s2 * acc.z) * k;
        o.w = (f.w + s1 * x1.w + s2 * acc.w) * k;
        ((float4*)avg)[gw * C4 + lane] = o;
    }
}

// ---------------- launch ----------------

extern "C" void kernel_launch(void* const* d_in, const int* in_sizes, int n_in,
                              void* d_out, int out_size) {
    const float* feat = (const float*)d_in[0];
    const float* W    = (const float*)d_in[1];
    const int*   src  = (const int*)d_in[2];
    const int*   dst  = (const int*)d_in[3];
    float*       avg  = (float*)d_out;

    const int N = in_sizes[0] / DD;   // 50000
    const int E = in_sizes[2];        // 800000
    const int nb = (N + 1023) / 1024; // 49

    // lazily create side stream + events once (first call runs outside capture)
    static cudaStream_t s2 = nullptr;
    static cudaEvent_t evFork = nullptr, evG0 = nullptr, evG1 = nullptr;
    static cudaEvent_t evS[NCHUNK] = {};
    if (!s2) {
        cudaStreamCreateWithFlags(&s2, cudaStreamNonBlocking);
        cudaEventCreateWithFlags(&evFork, cudaEventDisableTiming);
        cudaEventCreateWithFlags(&evG0, cudaEventDisableTiming);
        cudaEventCreateWithFlags(&evG1, cudaEventDisableTiming);
        for (int c = 0; c < NCHUNK; ++c)
            cudaEventCreateWithFlags(&evS[c], cudaEventDisableTiming);
    }

    void* pA; cudaGetSymbolAddress(&pA, g_bufA);
    void* pB; cudaGetSymbolAddress(&pB, g_bufB);
    void* pD; cudaGetSymbolAddress(&pD, g_bufD);

    // main chain: graph preprocessing
    init_k<<<(N + 255) / 256, 256>>>(W, N);

    // fork: layer-0 GEMM depends only on feat + g_Wt (from init_k)
    cudaEventRecord(evFork, 0);
    cudaStreamWaitEvent(s2, evFork, 0);
    gemm_k<<<(N + 59) / 60, 256, 0, s2>>>(feat, C4, 0, (float4*)pA, 0, N);
    cudaEventRecord(evG0, s2);

    count_k<<<(E + 255) / 256, 256>>>(dst, E);
    scanA_k<<<nb, 1024>>>(N);
    scanC_k<<<nb, 1024>>>(N, E);
    scatter_k<<<(E + 255) / 256, 256>>>(src, dst, E);

    // spmm0 needs full bufA (gathers arbitrary rows) + CSR
    cudaStreamWaitEvent(0, evG0, 0);

    // chunked spmm0 (main) overlapped with gemm1 (s2): spmm0 writes bufB
    // row-locally; gemm1 reads bufB row-locally and writes bufD (not bufA!)
    const int CH = (N + NCHUNK - 1) / NCHUNK;
    for (int c = 0; c < NCHUNK; ++c) {
        int rb = c * CH;
        int re = rb + CH; if (re > N) re = N;
        int rows = re - rb;
        spmm0_k<<<(rows * 32 + 255) / 256, 256>>>(rb, re);
        cudaEventRecord(evS[c], 0);
        cudaStreamWaitEvent(s2, evS[c], 0);
        gemm_k<<<(rows + 59) / 60, 256, 0, s2>>>((const float*)pB, CP, 1,
                                                 (float4*)pD, rb, re);
    }
    cudaEventRecord(evG1, s2);

    // spmm1 gathers arbitrary rows of bufD -> needs all gemm1 chunks
    cudaStreamWaitEvent(0, evG1, 0);
    spmm1_k<<<(N * 32 + 255) / 256, 256>>>(feat, avg, N);
}

// round 17
// speedup vs baseline: 1.1101x; 1.1101x over previous
#include <cuda_runtime.h>

// Problem constants (fixed by setup_inputs: N=50000, E=800000, D=100, 2 layers)
#define NMAX 50000
#define EMAX 800000
#define DD   100
#define C4   25      // D/4 float4 chunks per dense row (feat / output)
#define CP   32      // pitched float4 chunks per internal row (512B, line-aligned)
#define WPITCH 104   // padded pitch (floats) for transposed W rows in SMEM

typedef unsigned long long u64;

// ---- static device scratch (no runtime allocation allowed) ----
__device__ float g_bufA[NMAX * CP * 4];    // GEMM output / SpMM gather source (pitched)
__device__ float g_bufB[NMAX * CP * 4];    // spmm0 output x1 (gemm1 input)
__device__ int   g_cnt[NMAX];              // per-row edge counts
__device__ int   g_rowptr[NMAX + 1];       // CSR row pointers
__device__ float g_deginv[NMAX];           // 1/(cnt+1)  (self loop included)
__device__ int   g_col[EMAX];              // CSR column (src) indices
__device__ int   g_rank[EMAX];             // per-edge rank within its dst row
__device__ float g_sfac[NMAX];             // layer-0 per-row 1/max(norm,eps)
__device__ int   g_bsums[64];              // scan block sums

// ---------------- f32x2 helpers ----------------
__device__ __forceinline__ u64 dup2(float a) {
    u64 r; unsigned ai = __float_as_uint(a);
    asm("mov.b64 %0, {%1, %1};" : "=l"(r) : "r"(ai));
    return r;
}
__device__ __forceinline__ void ffma2(u64& acc, u64 a, u64 b) {
    asm("fma.rn.f32x2 %0, %1, %2, %0;" : "+l"(acc) : "l"(a), "l"(b));
}
__device__ __forceinline__ float2 unpk(u64 v) {
    unsigned lo, hi;
    asm("mov.b64 {%0, %1}, %2;" : "=r"(lo), "=r"(hi) : "l"(v));
    return make_float2(__uint_as_float(lo), __uint_as_float(hi));
}

// ---------------- preprocessing ----------------

// zero counts only (W transpose happens inside gemm_k's SMEM stage)
__global__ void init_k(int N) {
    int i = blockIdx.x * blockDim.x + threadIdx.x;
    if (i < N) g_cnt[i] = 0;
}

// histogram; the atomic's return value is the edge's rank within its row
__global__ void count_k(const int* __restrict__ dst, int E) {
    int i = blockIdx.x * blockDim.x + threadIdx.x;
    if (i < E) g_rank[i] = atomicAdd(&g_cnt[__ldg(&dst[i])], 1);
}

// scanA: per-1024-block exclusive scan (shfl-based), block totals -> g_bsums
__global__ void __launch_bounds__(1024) scanA_k(int N) {
    __shared__ int wsum[32];
    int tid = threadIdx.x, bid = blockIdx.x;
    int lane = tid & 31, wid = tid >> 5;
    int i = bid * 1024 + tid;
    int v = (i < N) ? g_cnt[i] : 0;

    int x = v;
    #pragma unroll
    for (int o = 1; o < 32; o <<= 1) {
        int t = __shfl_up_sync(0xffffffffu, x, o);
        if (lane >= o) x += t;
    }
    if (lane == 31) wsum[wid] = x;
    __syncthreads();
    if (wid == 0) {
        int s = wsum[lane];
        #pragma unroll
        for (int o = 1; o < 32; o <<= 1) {
            int t = __shfl_up_sync(0xffffffffu, s, o);
            if (lane >= o) s += t;
        }
        wsum[lane] = s;                     // inclusive scan of warp sums
    }
    __syncthreads();
    int excl = x - v + (wid ? wsum[wid - 1] : 0);

    if (i < N) {
        g_rowptr[i] = excl;                 // block-local exclusive
        g_deginv[i] = 1.0f / (float)(v + 1);
    }
    if (tid == 0) g_bsums[bid] = wsum[31];  // true block total
}

// scanC: each block adds the sum of its predecessor block totals (no spin)
__global__ void __launch_bounds__(1024) scanC_k(int N, int E) {
    __shared__ int s_off;
    int tid = threadIdx.x, bid = blockIdx.x;
    if (tid < 32) {
        int sum = 0;
        for (int p = tid; p < bid; p += 32) sum += g_bsums[p];
        #pragma unroll
        for (int o = 16; o; o >>= 1) sum += __shfl_xor_sync(0xffffffffu, sum, o);
        if (tid == 0) s_off = sum;
    }
    __syncthreads();
    int i = bid * 1024 + tid;
    if (i < N) g_rowptr[i] += s_off;
    if (i == 0) g_rowptr[N] = E;
}

// atomic-free CSR scatter: pos = rowptr[dst] + rank
__global__ void scatter_k(const int* __restrict__ src, const int* __restrict__ dst, int E) {
    int i = blockIdx.x * blockDim.x + threadIdx.x;
    if (i < E) {
        int d = __ldg(&dst[i]);
        int pos = __ldg(&g_rowptr[d]) + g_rank[i];
        g_col[pos] = __ldg(&src[i]);
    }
}

// ---------------- GEMM: g_bufA = x @ W[layer]^T  (packed f32x2) ----------------
// 60 rows per CTA; 250 active threads: cg = tid%25 (4 output cols), rg = tid/25
// (6 rows each). W is transposed into SMEM (k-major, padded pitch) on the fly:
// coalesced global reads, conflict-free k-major lane reads afterwards.
__global__ void __launch_bounds__(256) gemm_k(const float* __restrict__ xin, int xs4,
                                              const float* __restrict__ W, int layer,
                                              int N) {
    __shared__ float Ws[DD * WPITCH];   // 41.6 KB
    const float* wsrc = W + layer * DD * DD;
    for (int i = threadIdx.x; i < DD * DD; i += 256) {
        int j = i / DD;                 // output col
        int k = i - j * DD;             // k index
        Ws[k * WPITCH + j] = wsrc[i];   // transpose to k-major
    }
    __syncthreads();

    int tid = threadIdx.x;
    if (tid >= 250) return;
    int cg = tid % 25;
    int rg = tid / 25;                 // 0..9
    int row0 = blockIdx.x * 60 + rg * 6;

    const float4* x4 = (const float4*)xin;
    const double2* Wd = (const double2*)Ws;   // pitch: 26 double2 per k-row

    u64 a01[6], a23[6];
    int ridx[6];
    #pragma unroll
    for (int i = 0; i < 6; ++i) {
        a01[i] = 0ull; a23[i] = 0ull;
        int r = row0 + i;
        ridx[i] = (r < N) ? r : 0;     // clamp for safe loads; store is guarded
    }

    #pragma unroll 1
    for (int k4 = 0; k4 < 25; ++k4) {
        u64 w01[4], w23[4];
        #pragma unroll
        for (int kk = 0; kk < 4; ++kk) {
            double2 t = Wd[(k4 * 4 + kk) * 26 + cg];
            w01[kk] = __double_as_longlong(t.x);
            w23[kk] = __double_as_longlong(t.y);
        }
        #pragma unroll
        for (int i = 0; i < 6; ++i) {
            float4 xv = __ldg(&x4[ridx[i] * xs4 + k4]);
            u64 d0 = dup2(xv.x), d1 = dup2(xv.y), d2 = dup2(xv.z), d3 = dup2(xv.w);
            ffma2(a01[i], d0, w01[0]); ffma2(a23[i], d0, w23[0]);
            ffma2(a01[i], d1, w01[1]); ffma2(a23[i], d1, w23[1]);
            ffma2(a01[i], d2, w01[2]); ffma2(a23[i], d2, w23[2]);
            ffma2(a01[i], d3, w01[3]); ffma2(a23[i], d3, w23[3]);
        }
    }

    float4* y4 = (float4*)g_bufA;   // pitched CP float4 per row
    #pragma unroll
    for (int i = 0; i < 6; ++i) {
        int r = row0 + i;
        if (r < N) {
            float2 lo = unpk(a01[i]);
            float2 hi = unpk(a23[i]);
            y4[r * CP + cg] = make_float4(lo.x, lo.y, hi.x, hi.y);
        }
    }
}

// ---------------- shared SpMM core: acc = deg_inv*(self + gathered sum) ----------------
__device__ __forceinline__ float4 spmm_row(int gw, int lane, bool act) {
    const float4* x4 = (const float4*)g_bufA;

    float4 acc = make_float4(0.f, 0.f, 0.f, 0.f);
    if (act) acc = __ldg(&x4[gw * CP + lane]);     // self loop

    int beg = g_rowptr[gw];
    int end = g_rowptr[gw + 1];
    for (int base = beg; base < end; base += 32) {
        int idx = base + lane;
        int c = (idx < end) ? __ldg(&g_col[idx]) : 0;
        int m = end - base; if (m > 32) m = 32;
        int j = 0;
        for (; j + 3 < m; j += 4) {                // 4 gathers in flight
            int s0 = __shfl_sync(0xffffffffu, c, j);
            int s1 = __shfl_sync(0xffffffffu, c, j + 1);
            int s2 = __shfl_sync(0xffffffffu, c, j + 2);
            int s3 = __shfl_sync(0xffffffffu, c, j + 3);
            if (act) {
                float4 v0 = __ldg(&x4[s0 * CP + lane]);
                float4 v1 = __ldg(&x4[s1 * CP + lane]);
                float4 v2 = __ldg(&x4[s2 * CP + lane]);
                float4 v3 = __ldg(&x4[s3 * CP + lane]);
                acc.x += v0.x + v1.x; acc.y += v0.y + v1.y;
                acc.z += v0.z + v1.z; acc.w += v0.w + v1.w;
                acc.x += v2.x + v3.x; acc.y += v2.y + v3.y;
                acc.z += v2.z + v3.z; acc.w += v2.w + v3.w;
            }
        }
        for (; j < m; ++j) {
            int s0 = __shfl_sync(0xffffffffu, c, j);
            if (act) {
                float4 v0 = __ldg(&x4[s0 * CP + lane]);
                acc.x += v0.x; acc.y += v0.y; acc.z += v0.z; acc.w += v0.w;
            }
        }
    }

    float dinv = g_deginv[gw];
    acc.x *= dinv; acc.y *= dinv; acc.z *= dinv; acc.w *= dinv;
    return acc;
}

// layer 0: bufB = x1 (fp32) + sfac
__global__ void __launch_bounds__(256) spmm0_k(int N) {
    int gw = (blockIdx.x * blockDim.x + threadIdx.x) >> 5;
    int lane = threadIdx.x & 31;
    if (gw >= N) return;
    bool act = lane < C4;

    float4 acc = spmm_row(gw, lane, act);

    if (act) ((float4*)g_bufB)[gw * CP + lane] = acc;

    float p = act ? (acc.x * acc.x + acc.y * acc.y + acc.z * acc.z + acc.w * acc.w) : 0.f;
    #pragma unroll
    for (int o = 16; o; o >>= 1) p += __shfl_xor_sync(0xffffffffu, p, o);
    if (lane == 0) g_sfac[gw] = 1.0f / fmaxf(sqrtf(p), 1e-12f);
}

// layer 1 + fused finale: avg[r] = (feat[r] + s1*x1[r] + s2*x2[r]) / 3
__global__ void __launch_bounds__(256) spmm1_k(const float* __restrict__ feat,
                                               float* __restrict__ avg, int N) {
    int gw = (blockIdx.x * blockDim.x + threadIdx.x) >> 5;
    int lane = threadIdx.x & 31;
    if (gw >= N) return;
    bool act = lane < C4;

    float4 acc = spmm_row(gw, lane, act);   // x2 row

    float p = act ? (acc.x * acc.x + acc.y * acc.y + acc.z * acc.z + acc.w * acc.w) : 0.f;
    #pragma unroll
    for (int o = 16; o; o >>= 1) p += __shfl_xor_sync(0xffffffffu, p, o);
    float s2 = __shfl_sync(0xffffffffu,
                           (lane == 0) ? (1.0f / fmaxf(sqrtf(p), 1e-12f)) : 0.f, 0);

    if (act) {
        float s1 = __ldg(&g_sfac[gw]);
        float4 f  = ((const float4*)feat)[gw * C4 + lane];
        float4 x1 = ((const float4*)g_bufB)[gw * CP + lane];
        const float k = 1.0f / 3.0f;
        float4 o;
        o.x = (f.x + s1 * x1.x + s2 * acc.x) * k;
        o.y = (f.y + s1 * x1.y + s2 * acc.y) * k;
        o.z = (f.z + s1 * x1.z + s2 * acc.z) * k;
        o.w = (f.w + s1 * x1.w + s2 * acc.w) * k;
        ((float4*)avg)[gw * C4 + lane] = o;
    }
}

// ---------------- launch ----------------

extern "C" void kernel_launch(void* const* d_in, const int* in_sizes, int n_in,
                              void* d_out, int out_size) {
    const float* feat = (const float*)d_in[0];
    const float* W    = (const float*)d_in[1];
    const int*   src  = (const int*)d_in[2];
    const int*   dst  = (const int*)d_in[3];
    float*       avg  = (float*)d_out;

    const int N = in_sizes[0] / DD;   // 50000
    const int E = in_sizes[2];        // 800000
    const int nb = (N + 1023) / 1024; // 49

    // lazily create side stream + events once (first call runs outside capture)
    static cudaStream_t s2 = nullptr;
    static cudaEvent_t evFork = nullptr, evG0 = nullptr;
    if (!s2) {
        cudaStreamCreateWithFlags(&s2, cudaStreamNonBlocking);
        cudaEventCreateWithFlags(&evFork, cudaEventDisableTiming);
        cudaEventCreateWithFlags(&evG0, cudaEventDisableTiming);
    }

    void* pB; cudaGetSymbolAddress(&pB, g_bufB);

    const int gemm_blocks = (N + 59) / 60;
    const int spmm_blocks = (N * 32 + 255) / 256;

    // fork from the capture-origin stream FIRST (capture-legal side branch);
    // gemm0 has no kernel dependencies, so it runs concurrently with the
    // whole preprocessing chain below.
    cudaEventRecord(evFork, 0);
    cudaStreamWaitEvent(s2, evFork, 0);
    gemm_k<<<gemm_blocks, 256, 0, s2>>>(feat, C4, W, 0, N);  // bufA = feat @ W0^T
    cudaEventRecord(evG0, s2);

    // main chain: graph preprocessing (concurrent with gemm0)
    init_k<<<(N + 255) / 256, 256>>>(N);
    count_k<<<(E + 255) / 256, 256>>>(dst, E);
    scanA_k<<<nb, 1024>>>(N);
    scanC_k<<<nb, 1024>>>(N, E);
    scatter_k<<<(E + 255) / 256, 256>>>(src, dst, E);

    // join: spmm0 needs CSR (main) + bufA (s2)
    cudaStreamWaitEvent(0, evG0, 0);
    spmm0_k<<<spmm_blocks, 256>>>(N);                        // bufB = x1, sfac
    gemm_k<<<gemm_blocks, 256>>>((const float*)pB, CP, W, 1, N); // bufA = bufB @ W1^T
    spmm1_k<<<spmm_blocks, 256>>>(feat, avg, N);             // avg (fused finale)
}